// round 16
// baseline (speedup 1.0000x reference)
#include <cuda_runtime.h>

// ---------------------------------------------------------------------------
// DeepESN on B200 (sm_100a), round 16 = R15 + pipelined GEMM + per-slice deps.
//   drive GEMM: 128x128 tile, k-tile 16, register-prefetch double buffering
//     (LDG of tile i+1 overlaps FMA of tile i), one sync per tile.
//   recurrence: R15 core (own-chunk pre-compute, warp staging, tanh.approx)
//     with the group barrier replaced by PER-SLICE counters: each warp waits
//     only on the 1-2 producer CTAs of its 56-col window -> no step-wise
//     convoy on the slowest peer; slack pipelines through the slice graph.
// ---------------------------------------------------------------------------

#define BB   256
#define TT   512
#define UU   512
#define NCLS 10

#define NGRP 16
#define BCR  16
#define NSLC 8
#define NCOL 64
#define SSTR 516
#define RSTR 66
#define NTR  512
#define NT   256

#define AST2 132       // gemm stage stride (16 k rows x 132)

__device__ float        g_S0[(size_t)BB * TT * UU];
__device__ float        g_S1[(size_t)BB * TT * UU];
__device__ float        g_U [(size_t)BB * TT * UU];
__device__ float        g_H[3][2][BB * UU];
__device__ float        g_R[BB * 3 * UU];
__device__ unsigned int g_slc[3][NGRP][NSLC];   // per-slice step counters

__device__ __forceinline__ void dfma2(unsigned long long& d,
                                      unsigned long long a,
                                      unsigned long long b) {
    asm("fma.rn.f32x2 %0, %1, %2, %0;" : "+l"(d) : "l"(a), "l"(b));
}
__device__ __forceinline__ float dsum2(unsigned long long v) {
    float lo, hi;
    asm("mov.b64 {%0, %1}, %2;" : "=f"(lo), "=f"(hi) : "l"(v));
    return lo + hi;
}
__device__ __forceinline__ unsigned long long pk2(float x) {
    unsigned long long r;
    asm("mov.b64 %0, {%1, %1};" : "=l"(r) : "f"(x));
    return r;
}
__device__ __forceinline__ void upk2(unsigned long long v, float& lo, float& hi) {
    asm("mov.b64 {%0, %1}, %2;" : "=f"(lo), "=f"(hi) : "l"(v));
}
__device__ __forceinline__ float tanh_fast(float x) {
    float r;
    asm("tanh.approx.f32 %0, %1;" : "=f"(r) : "f"(x));
    return r;
}

// ============================================================================
// Drive GEMM: g_U[M,512] = A[M,K] @ W[K,512] + bias.  Tile 128x128, k-tile 16,
// register-prefetch double buffering. 256 threads, thread = 8 rows x 8 cols.
// ============================================================================
__global__ void __launch_bounds__(NT)
drive_gemm(const float* __restrict__ x, const float* __restrict__ W,
           const float* __restrict__ bias, int K, int layer, int n_base)
{
    __shared__ float As[2][16 * AST2];    // transposed: As[k][row]
    __shared__ float Bs[2][16 * AST2];    // Bs[k][col]

    const float* A = (layer == 0) ? x : ((layer == 1) ? g_S0 : g_S1);
    float*       C = g_U;

    const int tid = threadIdx.x;
    const int tx  = tid & 15;
    const int ty  = tid >> 4;
    const int m0  = blockIdx.y * 128;
    const int n0  = n_base + blockIdx.x * 128;

    // A stage: f4 idx = tid*2 + i -> row = idx>>2, kq = idx&3
    const int ar0 = (tid * 2) >> 2;
    const int aq0 = (tid * 2) & 3;
    // B stage: f4 idx = tid*2 + i -> k = idx>>5, c4 = idx&31
    const int bk0 = (tid * 2) >> 5;
    const int bc0 = (tid * 2) & 31;

    const int nt = K >> 4;
    float4 ra[2], rb[2];

    // prologue: load tile 0
#pragma unroll
    for (int i = 0; i < 2; ++i) {
        int idx = tid * 2 + i;
        ra[i] = __ldg(reinterpret_cast<const float4*>(
                          A + (size_t)(m0 + (idx >> 2)) * K) + (idx & 3));
        rb[i] = __ldg(reinterpret_cast<const float4*>(
                          W + (size_t)(idx >> 5) * UU + n0) + (idx & 31));
    }
    {
#pragma unroll
        for (int i = 0; i < 2; ++i) {
            int row = (i == 0) ? ar0 : ((tid * 2 + 1) >> 2);
            int kq  = (i == 0) ? aq0 : ((tid * 2 + 1) & 3);
            As[0][(kq * 4 + 0) * AST2 + row] = ra[i].x;
            As[0][(kq * 4 + 1) * AST2 + row] = ra[i].y;
            As[0][(kq * 4 + 2) * AST2 + row] = ra[i].z;
            As[0][(kq * 4 + 3) * AST2 + row] = ra[i].w;
            int k  = (i == 0) ? bk0 : ((tid * 2 + 1) >> 5);
            int c4 = (i == 0) ? bc0 : ((tid * 2 + 1) & 31);
            *reinterpret_cast<float4*>(Bs[0] + k * AST2 + c4 * 4) = rb[i];
        }
    }
    __syncthreads();

    unsigned long long acc[4][8];
#pragma unroll
    for (int p = 0; p < 4; ++p)
#pragma unroll
        for (int c = 0; c < 8; ++c) acc[p][c] = 0ull;

    for (int it = 0; it < nt; ++it) {
        const int cur = it & 1;
        const int kt  = (it + 1) << 4;

        // prefetch next tile into registers (overlaps the FMA block below)
        if (it + 1 < nt) {
#pragma unroll
            for (int i = 0; i < 2; ++i) {
                int idx = tid * 2 + i;
                ra[i] = __ldg(reinterpret_cast<const float4*>(
                                  A + (size_t)(m0 + (idx >> 2)) * K + kt)
                              + (idx & 3));
                rb[i] = __ldg(reinterpret_cast<const float4*>(
                                  W + (size_t)(kt + (idx >> 5)) * UU + n0)
                              + (idx & 31));
            }
        }

        // compute current tile
#pragma unroll
        for (int k = 0; k < 16; ++k) {
            unsigned long long a[4];
#pragma unroll
            for (int p = 0; p < 4; ++p)
                a[p] = *reinterpret_cast<const unsigned long long*>(
                           As[cur] + k * AST2 + ty * 8 + 2 * p);
            float4 b0 = *reinterpret_cast<const float4*>(Bs[cur] + k * AST2 + tx * 8);
            float4 b1 = *reinterpret_cast<const float4*>(Bs[cur] + k * AST2 + tx * 8 + 4);
            unsigned long long bb[8] = {pk2(b0.x), pk2(b0.y), pk2(b0.z), pk2(b0.w),
                                        pk2(b1.x), pk2(b1.y), pk2(b1.z), pk2(b1.w)};
#pragma unroll
            for (int p = 0; p < 4; ++p)
#pragma unroll
                for (int c = 0; c < 8; ++c)
                    dfma2(acc[p][c], a[p], bb[c]);
        }

        // store prefetched tile into the other buffer
        if (it + 1 < nt) {
            const int nxt = cur ^ 1;
#pragma unroll
            for (int i = 0; i < 2; ++i) {
                int idx = tid * 2 + i;
                int row = idx >> 2, kq = idx & 3;
                As[nxt][(kq * 4 + 0) * AST2 + row] = ra[i].x;
                As[nxt][(kq * 4 + 1) * AST2 + row] = ra[i].y;
                As[nxt][(kq * 4 + 2) * AST2 + row] = ra[i].z;
                As[nxt][(kq * 4 + 3) * AST2 + row] = ra[i].w;
                int k = idx >> 5, c4 = idx & 31;
                *reinterpret_cast<float4*>(Bs[nxt] + k * AST2 + c4 * 4) = rb[i];
            }
        }
        __syncthreads();
    }

    float4 bv0 = __ldg(reinterpret_cast<const float4*>(bias + n0 + tx * 8));
    float4 bv1 = __ldg(reinterpret_cast<const float4*>(bias + n0 + tx * 8 + 4));
    const float bb[8] = {bv0.x, bv0.y, bv0.z, bv0.w, bv1.x, bv1.y, bv1.z, bv1.w};
#pragma unroll
    for (int p = 0; p < 4; ++p) {
        float lo[8], hi[8];
#pragma unroll
        for (int c = 0; c < 8; ++c) {
            upk2(acc[p][c], lo[c], hi[c]);
            lo[c] += bb[c]; hi[c] += bb[c];
        }
        size_t r0 = (size_t)(m0 + ty * 8 + 2 * p) * UU + n0 + tx * 8;
        *reinterpret_cast<float4*>(C + r0)          = make_float4(lo[0], lo[1], lo[2], lo[3]);
        *reinterpret_cast<float4*>(C + r0 + 4)      = make_float4(lo[4], lo[5], lo[6], lo[7]);
        *reinterpret_cast<float4*>(C + r0 + UU)     = make_float4(hi[0], hi[1], hi[2], hi[3]);
        *reinterpret_cast<float4*>(C + r0 + UU + 4) = make_float4(hi[4], hi[5], hi[6], hi[7]);
    }
}

// ============================================================================
// Recurrence: per-slice dependency counters + warp staging (R15 core).
// ============================================================================
__global__ void __launch_bounds__(NTR, 1)
recur_kernel(const float* __restrict__ Wrec, int layer)
{
    extern __shared__ float smem[];
    float* sWT  = smem;                       // [64][SSTR]
    float* sSt  = smem + NCOL * SSTR;         // [16][SSTR]
    float* sRed = sSt + BCR * SSTR;           // [128][RSTR]

    const float* u    = g_U;
    float*       sout = (layer == 0) ? g_S0 : ((layer == 1) ? g_S1 : (float*)0);
    float* const hb0  = g_H[layer][0];
    float* const hb1  = g_H[layer][1];

    const int tid  = threadIdx.x;
    const int lane = tid & 31;
    const int wid  = tid >> 5;
    const int rg   = wid & 1;                 // rowgroup
    const int kc   = wid >> 1;                // chunk id 0..7
    const int grp  = blockIdx.x >> 3;
    const int sl   = blockIdx.x & 7;
    const int b0   = grp * BCR;
    const int col0 = sl * NCOL;

    unsigned int* const slcrow = &g_slc[layer][grp][0];
    const int fbase = col0 + 64 + kc * 56;    // foreign window start (unmasked)
    const int sA = (fbase & 511) >> 6;        // producer slice(s) of my window
    const int sB = ((fbase + 52) & 511) >> 6;
    unsigned int* const pA = &slcrow[sA];
    unsigned int* const pB = &slcrow[sB];

    const int fi = tid >> 5;                  // finalize row 0..15
    const int fj = lane;                      // finalize cols (fj, fj+32)

    // weight slice: sWT[c][k] = Wrec[k][col0+c]
    for (int idx = tid; idx < NCOL * UU; idx += NTR) {
        int c = idx & 63, k = idx >> 6;
        sWT[c * SSTR + k] = Wrec[(size_t)k * UU + col0 + c];
    }
    // zero the stage (h(0) = 0; all steps uniform incl. t=0)
    for (int idx = tid; idx < BCR * 512; idx += NTR) {
        int i = idx >> 9, c = idx & 511;
        sSt[i * SSTR + c] = 0.0f;
    }
    __syncthreads();

    for (int t = 0; t < TT; ++t) {
        const int p = t & 1;
        const float* hsrc = p ? hb1 : hb0;
        float*       hdst = p ? hb0 : hb1;
        const size_t m = (size_t)(b0 + fi) * TT + t;

        // ---- phase 1 (pre-wait): own 8-k slice from carried own cols ----
        unsigned long long acc[8][2];
#pragma unroll
        for (int r = 0; r < 8; ++r) { acc[r][0] = 0ull; acc[r][1] = 0ull; }
        {
            const int kown = col0 + kc * 8;
            const ulonglong2* w0p = reinterpret_cast<const ulonglong2*>(
                sWT + lane * SSTR + kown);
            const ulonglong2* w1p = reinterpret_cast<const ulonglong2*>(
                sWT + (lane + 32) * SSTR + kown);
            const float* arow = sSt + rg * 8 * SSTR + kown;
#pragma unroll
            for (int q = 0; q < 2; ++q) {
                ulonglong2 w0 = w0p[q];
                ulonglong2 w1 = w1p[q];
#pragma unroll
                for (int r = 0; r < 8; ++r) {
                    ulonglong2 a = *reinterpret_cast<const ulonglong2*>(
                        arow + r * SSTR + 4 * q);
                    dfma2(acc[r][0], a.x, w0.x);
                    dfma2(acc[r][0], a.y, w0.y);
                    dfma2(acc[r][1], a.x, w1.x);
                    dfma2(acc[r][1], a.y, w1.y);
                }
            }
        }

        // u prefetch (constant during launch)
        const float u0 = __ldg(u + m * UU + col0 + fj);
        const float u1 = __ldg(u + m * UU + col0 + fj + 32);

        // ---- per-warp wait on this window's 1-2 producer slices ----
        if (t > 0) {
            const unsigned int tgt = (unsigned int)t;
            unsigned int v;
            do {
                asm volatile("ld.acquire.gpu.u32 %0, [%1];"
                             : "=r"(v) : "l"(pA));
                if (v >= tgt) break;
                __nanosleep(16);
            } while (true);
            if (pB != pA) {
                do {
                    asm volatile("ld.acquire.gpu.u32 %0, [%1];"
                                 : "=r"(v) : "l"(pB));
                    if (v >= tgt) break;
                    __nanosleep(16);
                } while (true);
            }

            // stage own 8 rows x 56 foreign cols
            const int grow = b0 + rg * 8;
            for (int idx = lane; idx < 112; idx += 32) {
                int i = idx / 14, q = idx - i * 14;
                int c = (fbase + 4 * q) & 511;
                float4 v4 = __ldcg(reinterpret_cast<const float4*>(
                                       hsrc + (size_t)(grow + i) * UU + c));
                *reinterpret_cast<float4*>(sSt + (rg * 8 + i) * SSTR + c) = v4;
            }
            __syncwarp();
        }

        // ---- phase 2: foreign 56-k chunk (circular remap) ----
        {
            const float* wl0 = sWT + lane * SSTR;
            const float* wl1 = sWT + (lane + 32) * SSTR;
            const float* ar0 = sSt + rg * 8 * SSTR;
#pragma unroll 2
            for (int q = 0; q < 14; ++q) {
                const int kq = (fbase + 4 * q) & 511;
                ulonglong2 w0 = *reinterpret_cast<const ulonglong2*>(wl0 + kq);
                ulonglong2 w1 = *reinterpret_cast<const ulonglong2*>(wl1 + kq);
                const float* arow = ar0 + kq;
#pragma unroll
                for (int r = 0; r < 8; ++r) {
                    ulonglong2 a = *reinterpret_cast<const ulonglong2*>(
                        arow + r * SSTR);
                    dfma2(acc[r][0], a.x, w0.x);
                    dfma2(acc[r][0], a.y, w0.y);
                    dfma2(acc[r][1], a.x, w1.x);
                    dfma2(acc[r][1], a.y, w1.y);
                }
            }
        }

        // ---- partials ----
        {
            float* base = sRed + (size_t)(kc * 16 + rg * 8) * RSTR + lane * 2;
#pragma unroll
            for (int r = 0; r < 8; ++r) {
                float2 v;
                v.x = dsum2(acc[r][0]);
                v.y = dsum2(acc[r][1]);
                *reinterpret_cast<float2*>(base + r * RSTR) = v;
            }
        }
        __syncthreads();                       // [S3]

        // ---- finalize: 2 outputs per thread ----
        {
            float z0 = u0, z1 = u1;
            const float* rb = sRed + (size_t)fi * RSTR + fj * 2;
#pragma unroll
            for (int k2 = 0; k2 < 8; ++k2) {
                float2 pv = *reinterpret_cast<const float2*>(
                    rb + (size_t)k2 * (16 * RSTR));
                z0 += pv.x; z1 += pv.y;
            }
            const float hold0 = sSt[fi * SSTR + col0 + fj];
            const float hold1 = sSt[fi * SSTR + col0 + fj + 32];
            float hn0 = hold0 * 0.1f + 0.9f * tanh_fast(z0);
            float hn1 = hold1 * 0.1f + 0.9f * tanh_fast(z1);
            size_t gh = (size_t)(b0 + fi) * UU + col0 + fj;
            hdst[gh]      = hn0;
            hdst[gh + 32] = hn1;
            sSt[fi * SSTR + col0 + fj]      = hn0;   // own-slice carry
            sSt[fi * SSTR + col0 + fj + 32] = hn1;
            if (sout) {
                sout[m * UU + col0 + fj]      = hn0;
                sout[m * UU + col0 + fj + 32] = hn1;
            }
            if (t == TT - 1) {
                size_t gr = (size_t)(b0 + fi) * (3 * UU) + layer * UU + col0 + fj;
                g_R[gr]      = hn0;
                g_R[gr + 32] = hn1;
            }
        }

        // ---- publish this slice for step t ----  [S4]
        if (t < TT - 1) {
            __syncthreads();
            if (tid == 0) {
                asm volatile("fence.acq_rel.gpu;" ::: "memory");
                atomicAdd(&slcrow[sl], 1u);
            }
        }
    }
}

__global__ void init_kernel() {
    int idx = blockIdx.x * blockDim.x + threadIdx.x;
    if (idx < 3 * 2 * BB * UU) ((float*)g_H)[idx] = 0.0f;
    if (idx < 3 * NGRP * NSLC) ((unsigned int*)g_slc)[idx] = 0u;
}

__global__ void readout_kernel(const float* __restrict__ Wout,
                               const float* __restrict__ bout,
                               float* __restrict__ out) {
    __shared__ float red[NCLS][NT];
    int b = blockIdx.x, tid = threadIdx.x;
    float part[NCLS];
#pragma unroll
    for (int c = 0; c < NCLS; ++c) part[c] = 0.0f;
    for (int k = tid; k < 3 * UU; k += NT) {
        float r = g_R[(size_t)b * 3 * UU + k];
#pragma unroll
        for (int c = 0; c < NCLS; ++c) part[c] += r * Wout[k * NCLS + c];
    }
#pragma unroll
    for (int c = 0; c < NCLS; ++c) red[c][tid] = part[c];
    __syncthreads();
    if (tid < NCLS) {
        float s = 0.0f;
        for (int i = 0; i < NT; ++i) s += red[tid][i];
        out[b * NCLS + tid] = s + bout[tid];
    }
}

extern "C" void kernel_launch(void* const* d_in, const int* in_sizes, int n_in,
                              void* d_out, int out_size) {
    (void)in_sizes; (void)n_in; (void)out_size;
    const float* x    = (const float*)d_in[0];
    const float* Win0 = (const float*)d_in[1];
    const float* W0   = (const float*)d_in[2];
    const float* b0   = (const float*)d_in[3];
    const float* Win1 = (const float*)d_in[4];
    const float* W1   = (const float*)d_in[5];
    const float* b1   = (const float*)d_in[6];
    const float* Win2 = (const float*)d_in[7];
    const float* W2   = (const float*)d_in[8];
    const float* b2   = (const float*)d_in[9];
    const float* Wout = (const float*)d_in[10];
    const float* bout = (const float*)d_in[11];
    float* out = (float*)d_out;

    // recur smem: 64x516 + 16x516 + 128x66 = 198,912 B (1 CTA/SM)
    const int smem = (NCOL * SSTR + BCR * SSTR + 128 * RSTR) * (int)sizeof(float);
    static int attr_done = 0;
    if (!attr_done) {
        cudaFuncSetAttribute(recur_kernel,
                             cudaFuncAttributeMaxDynamicSharedMemorySize, smem);
        attr_done = 1;
    }

    const dim3 ggrid(4, (BB * TT) / 128);
    const dim3 hgrid(2, (BB * TT) / 128);

    init_kernel<<<3072, NT>>>();                             // launch 1
    drive_gemm<<<hgrid, NT>>>(x, Win0, b0, 64, 0, 0);        // launch 2
    drive_gemm<<<hgrid, NT>>>(x, Win0, b0, 64, 0, 256);      // launch 3
    recur_kernel<<<NGRP * NSLC, NTR, smem>>>(W0, 0);         // launch 4 (ncu aim)
    drive_gemm<<<ggrid, NT>>>(x, Win1, b1, 512, 1, 0);
    recur_kernel<<<NGRP * NSLC, NTR, smem>>>(W1, 1);
    drive_gemm<<<ggrid, NT>>>(x, Win2, b2, 512, 2, 0);
    recur_kernel<<<NGRP * NSLC, NTR, smem>>>(W2, 2);
    readout_kernel<<<BB, NT>>>(Wout, bout, out);
}

// round 17
// speedup vs baseline: 1.0676x; 1.0676x over previous
#include <cuda_runtime.h>

// ---------------------------------------------------------------------------
// DeepESN on B200 (sm_100a), round 17 = R16 recur (per-slice deps, KEPT) +
// R15 GEMM (k-tile 8, register-prefetch REVERTED: it pushed past 128 regs and
// collapsed GEMM occupancy, costing more than the prefetch gained).
// ---------------------------------------------------------------------------

#define BB   256
#define TT   512
#define UU   512
#define NCLS 10

#define NGRP 16
#define BCR  16
#define NSLC 8
#define NCOL 64
#define SSTR 516
#define RSTR 66
#define NTR  512
#define NT   256

#define AST2 132
#define BST2 132

__device__ float        g_S0[(size_t)BB * TT * UU];
__device__ float        g_S1[(size_t)BB * TT * UU];
__device__ float        g_U [(size_t)BB * TT * UU];
__device__ float        g_H[3][2][BB * UU];
__device__ float        g_R[BB * 3 * UU];
__device__ unsigned int g_slc[3][NGRP][NSLC];   // per-slice step counters

__device__ __forceinline__ void dfma2(unsigned long long& d,
                                      unsigned long long a,
                                      unsigned long long b) {
    asm("fma.rn.f32x2 %0, %1, %2, %0;" : "+l"(d) : "l"(a), "l"(b));
}
__device__ __forceinline__ float dsum2(unsigned long long v) {
    float lo, hi;
    asm("mov.b64 {%0, %1}, %2;" : "=f"(lo), "=f"(hi) : "l"(v));
    return lo + hi;
}
__device__ __forceinline__ unsigned long long pk2(float x) {
    unsigned long long r;
    asm("mov.b64 %0, {%1, %1};" : "=l"(r) : "f"(x));
    return r;
}
__device__ __forceinline__ void upk2(unsigned long long v, float& lo, float& hi) {
    asm("mov.b64 {%0, %1}, %2;" : "=f"(lo), "=f"(hi) : "l"(v));
}
__device__ __forceinline__ float tanh_fast(float x) {
    float r;
    asm("tanh.approx.f32 %0, %1;" : "=f"(r) : "f"(x));
    return r;
}

// ============================================================================
// Drive GEMM (R15 version): g_U[M,512] = A[M,K] @ W[K,512] + bias.
// Tile 128x128, k-tile 8, 256 threads, thread = 8 rows x 8 cols.
// ============================================================================
__global__ void __launch_bounds__(NT)
drive_gemm(const float* __restrict__ x, const float* __restrict__ W,
           const float* __restrict__ bias, int K, int layer, int n_base)
{
    __shared__ float As[8 * AST2];
    __shared__ float Bs[8 * BST2];

    const float* A = (layer == 0) ? x : ((layer == 1) ? g_S0 : g_S1);
    float*       C = g_U;

    const int tid = threadIdx.x;
    const int tx  = tid & 15;
    const int ty  = tid >> 4;
    const int m0  = blockIdx.y * 128;
    const int n0  = n_base + blockIdx.x * 128;

    const int arow  = tid >> 1;
    const int ahalf = tid & 1;
    const int bk    = tid >> 5;
    const int bc4   = tid & 31;

    unsigned long long acc[4][8];
#pragma unroll
    for (int p = 0; p < 4; ++p)
#pragma unroll
        for (int c = 0; c < 8; ++c) acc[p][c] = 0ull;

    for (int kt = 0; kt < K; kt += 8) {
        {
            float4 va = __ldg(reinterpret_cast<const float4*>(
                                  A + (size_t)(m0 + arow) * K + kt + ahalf * 4));
            As[(ahalf * 4 + 0) * AST2 + arow] = va.x;
            As[(ahalf * 4 + 1) * AST2 + arow] = va.y;
            As[(ahalf * 4 + 2) * AST2 + arow] = va.z;
            As[(ahalf * 4 + 3) * AST2 + arow] = va.w;
            float4 vb = __ldg(reinterpret_cast<const float4*>(
                                  W + (size_t)(kt + bk) * UU + n0 + bc4 * 4));
            *reinterpret_cast<float4*>(Bs + bk * BST2 + bc4 * 4) = vb;
        }
        __syncthreads();

#pragma unroll
        for (int k = 0; k < 8; ++k) {
            unsigned long long a[4];
#pragma unroll
            for (int p = 0; p < 4; ++p)
                a[p] = *reinterpret_cast<const unsigned long long*>(
                           As + k * AST2 + ty * 8 + 2 * p);
            float4 b0 = *reinterpret_cast<const float4*>(Bs + k * BST2 + tx * 8);
            float4 b1 = *reinterpret_cast<const float4*>(Bs + k * BST2 + tx * 8 + 4);
            unsigned long long bb[8] = {pk2(b0.x), pk2(b0.y), pk2(b0.z), pk2(b0.w),
                                        pk2(b1.x), pk2(b1.y), pk2(b1.z), pk2(b1.w)};
#pragma unroll
            for (int p = 0; p < 4; ++p)
#pragma unroll
                for (int c = 0; c < 8; ++c)
                    dfma2(acc[p][c], a[p], bb[c]);
        }
        __syncthreads();
    }

    float4 bv0 = __ldg(reinterpret_cast<const float4*>(bias + n0 + tx * 8));
    float4 bv1 = __ldg(reinterpret_cast<const float4*>(bias + n0 + tx * 8 + 4));
    const float bb[8] = {bv0.x, bv0.y, bv0.z, bv0.w, bv1.x, bv1.y, bv1.z, bv1.w};
#pragma unroll
    for (int p = 0; p < 4; ++p) {
        float lo[8], hi[8];
#pragma unroll
        for (int c = 0; c < 8; ++c) {
            upk2(acc[p][c], lo[c], hi[c]);
            lo[c] += bb[c]; hi[c] += bb[c];
        }
        size_t r0 = (size_t)(m0 + ty * 8 + 2 * p) * UU + n0 + tx * 8;
        *reinterpret_cast<float4*>(C + r0)          = make_float4(lo[0], lo[1], lo[2], lo[3]);
        *reinterpret_cast<float4*>(C + r0 + 4)      = make_float4(lo[4], lo[5], lo[6], lo[7]);
        *reinterpret_cast<float4*>(C + r0 + UU)     = make_float4(hi[0], hi[1], hi[2], hi[3]);
        *reinterpret_cast<float4*>(C + r0 + UU + 4) = make_float4(hi[4], hi[5], hi[6], hi[7]);
    }
}

// ============================================================================
// Recurrence (R16 version, kept): per-slice dependency counters + warp staging.
// ============================================================================
__global__ void __launch_bounds__(NTR, 1)
recur_kernel(const float* __restrict__ Wrec, int layer)
{
    extern __shared__ float smem[];
    float* sWT  = smem;                       // [64][SSTR]
    float* sSt  = smem + NCOL * SSTR;         // [16][SSTR]
    float* sRed = sSt + BCR * SSTR;           // [128][RSTR]

    const float* u    = g_U;
    float*       sout = (layer == 0) ? g_S0 : ((layer == 1) ? g_S1 : (float*)0);
    float* const hb0  = g_H[layer][0];
    float* const hb1  = g_H[layer][1];

    const int tid  = threadIdx.x;
    const int lane = tid & 31;
    const int wid  = tid >> 5;
    const int rg   = wid & 1;                 // rowgroup
    const int kc   = wid >> 1;                // chunk id 0..7
    const int grp  = blockIdx.x >> 3;
    const int sl   = blockIdx.x & 7;
    const int b0   = grp * BCR;
    const int col0 = sl * NCOL;

    unsigned int* const slcrow = &g_slc[layer][grp][0];
    const int fbase = col0 + 64 + kc * 56;    // foreign window start (unmasked)
    const int sA = (fbase & 511) >> 6;        // producer slice(s) of my window
    const int sB = ((fbase + 52) & 511) >> 6;
    unsigned int* const pA = &slcrow[sA];
    unsigned int* const pB = &slcrow[sB];

    const int fi = tid >> 5;                  // finalize row 0..15
    const int fj = lane;                      // finalize cols (fj, fj+32)

    // weight slice: sWT[c][k] = Wrec[k][col0+c]
    for (int idx = tid; idx < NCOL * UU; idx += NTR) {
        int c = idx & 63, k = idx >> 6;
        sWT[c * SSTR + k] = Wrec[(size_t)k * UU + col0 + c];
    }
    // zero the stage (h(0) = 0; all steps uniform incl. t=0)
    for (int idx = tid; idx < BCR * 512; idx += NTR) {
        int i = idx >> 9, c = idx & 511;
        sSt[i * SSTR + c] = 0.0f;
    }
    __syncthreads();

    for (int t = 0; t < TT; ++t) {
        const int p = t & 1;
        const float* hsrc = p ? hb1 : hb0;
        float*       hdst = p ? hb0 : hb1;
        const size_t m = (size_t)(b0 + fi) * TT + t;

        // ---- phase 1 (pre-wait): own 8-k slice from carried own cols ----
        unsigned long long acc[8][2];
#pragma unroll
        for (int r = 0; r < 8; ++r) { acc[r][0] = 0ull; acc[r][1] = 0ull; }
        {
            const int kown = col0 + kc * 8;
            const ulonglong2* w0p = reinterpret_cast<const ulonglong2*>(
                sWT + lane * SSTR + kown);
            const ulonglong2* w1p = reinterpret_cast<const ulonglong2*>(
                sWT + (lane + 32) * SSTR + kown);
            const float* arow = sSt + rg * 8 * SSTR + kown;
#pragma unroll
            for (int q = 0; q < 2; ++q) {
                ulonglong2 w0 = w0p[q];
                ulonglong2 w1 = w1p[q];
#pragma unroll
                for (int r = 0; r < 8; ++r) {
                    ulonglong2 a = *reinterpret_cast<const ulonglong2*>(
                        arow + r * SSTR + 4 * q);
                    dfma2(acc[r][0], a.x, w0.x);
                    dfma2(acc[r][0], a.y, w0.y);
                    dfma2(acc[r][1], a.x, w1.x);
                    dfma2(acc[r][1], a.y, w1.y);
                }
            }
        }

        // u prefetch (constant during launch)
        const float u0 = __ldg(u + m * UU + col0 + fj);
        const float u1 = __ldg(u + m * UU + col0 + fj + 32);

        // ---- per-warp wait on this window's 1-2 producer slices ----
        if (t > 0) {
            const unsigned int tgt = (unsigned int)t;
            unsigned int v;
            do {
                asm volatile("ld.acquire.gpu.u32 %0, [%1];"
                             : "=r"(v) : "l"(pA));
                if (v >= tgt) break;
                __nanosleep(16);
            } while (true);
            if (pB != pA) {
                do {
                    asm volatile("ld.acquire.gpu.u32 %0, [%1];"
                                 : "=r"(v) : "l"(pB));
                    if (v >= tgt) break;
                    __nanosleep(16);
                } while (true);
            }

            // stage own 8 rows x 56 foreign cols
            const int grow = b0 + rg * 8;
            for (int idx = lane; idx < 112; idx += 32) {
                int i = idx / 14, q = idx - i * 14;
                int c = (fbase + 4 * q) & 511;
                float4 v4 = __ldcg(reinterpret_cast<const float4*>(
                                       hsrc + (size_t)(grow + i) * UU + c));
                *reinterpret_cast<float4*>(sSt + (rg * 8 + i) * SSTR + c) = v4;
            }
            __syncwarp();
        }

        // ---- phase 2: foreign 56-k chunk (circular remap) ----
        {
            const float* wl0 = sWT + lane * SSTR;
            const float* wl1 = sWT + (lane + 32) * SSTR;
            const float* ar0 = sSt + rg * 8 * SSTR;
#pragma unroll 2
            for (int q = 0; q < 14; ++q) {
                const int kq = (fbase + 4 * q) & 511;
                ulonglong2 w0 = *reinterpret_cast<const ulonglong2*>(wl0 + kq);
                ulonglong2 w1 = *reinterpret_cast<const ulonglong2*>(wl1 + kq);
                const float* arow = ar0 + kq;
#pragma unroll
                for (int r = 0; r < 8; ++r) {
                    ulonglong2 a = *reinterpret_cast<const ulonglong2*>(
                        arow + r * SSTR);
                    dfma2(acc[r][0], a.x, w0.x);
                    dfma2(acc[r][0], a.y, w0.y);
                    dfma2(acc[r][1], a.x, w1.x);
                    dfma2(acc[r][1], a.y, w1.y);
                }
            }
        }

        // ---- partials ----
        {
            float* base = sRed + (size_t)(kc * 16 + rg * 8) * RSTR + lane * 2;
#pragma unroll
            for (int r = 0; r < 8; ++r) {
                float2 v;
                v.x = dsum2(acc[r][0]);
                v.y = dsum2(acc[r][1]);
                *reinterpret_cast<float2*>(base + r * RSTR) = v;
            }
        }
        __syncthreads();                       // [S3]

        // ---- finalize: 2 outputs per thread ----
        {
            float z0 = u0, z1 = u1;
            const float* rb = sRed + (size_t)fi * RSTR + fj * 2;
#pragma unroll
            for (int k2 = 0; k2 < 8; ++k2) {
                float2 pv = *reinterpret_cast<const float2*>(
                    rb + (size_t)k2 * (16 * RSTR));
                z0 += pv.x; z1 += pv.y;
            }
            const float hold0 = sSt[fi * SSTR + col0 + fj];
            const float hold1 = sSt[fi * SSTR + col0 + fj + 32];
            float hn0 = hold0 * 0.1f + 0.9f * tanh_fast(z0);
            float hn1 = hold1 * 0.1f + 0.9f * tanh_fast(z1);
            size_t gh = (size_t)(b0 + fi) * UU + col0 + fj;
            hdst[gh]      = hn0;
            hdst[gh + 32] = hn1;
            sSt[fi * SSTR + col0 + fj]      = hn0;   // own-slice carry
            sSt[fi * SSTR + col0 + fj + 32] = hn1;
            if (sout) {
                sout[m * UU + col0 + fj]      = hn0;
                sout[m * UU + col0 + fj + 32] = hn1;
            }
            if (t == TT - 1) {
                size_t gr = (size_t)(b0 + fi) * (3 * UU) + layer * UU + col0 + fj;
                g_R[gr]      = hn0;
                g_R[gr + 32] = hn1;
            }
        }

        // ---- publish this slice for step t ----  [S4]
        if (t < TT - 1) {
            __syncthreads();
            if (tid == 0) {
                asm volatile("fence.acq_rel.gpu;" ::: "memory");
                atomicAdd(&slcrow[sl], 1u);
            }
        }
    }
}

__global__ void init_kernel() {
    int idx = blockIdx.x * blockDim.x + threadIdx.x;
    if (idx < 3 * 2 * BB * UU) ((float*)g_H)[idx] = 0.0f;
    if (idx < 3 * NGRP * NSLC) ((unsigned int*)g_slc)[idx] = 0u;
}

__global__ void readout_kernel(const float* __restrict__ Wout,
                               const float* __restrict__ bout,
                               float* __restrict__ out) {
    __shared__ float red[NCLS][NT];
    int b = blockIdx.x, tid = threadIdx.x;
    float part[NCLS];
#pragma unroll
    for (int c = 0; c < NCLS; ++c) part[c] = 0.0f;
    for (int k = tid; k < 3 * UU; k += NT) {
        float r = g_R[(size_t)b * 3 * UU + k];
#pragma unroll
        for (int c = 0; c < NCLS; ++c) part[c] += r * Wout[k * NCLS + c];
    }
#pragma unroll
    for (int c = 0; c < NCLS; ++c) red[c][tid] = part[c];
    __syncthreads();
    if (tid < NCLS) {
        float s = 0.0f;
        for (int i = 0; i < NT; ++i) s += red[tid][i];
        out[b * NCLS + tid] = s + bout[tid];
    }
}

extern "C" void kernel_launch(void* const* d_in, const int* in_sizes, int n_in,
                              void* d_out, int out_size) {
    (void)in_sizes; (void)n_in; (void)out_size;
    const float* x    = (const float*)d_in[0];
    const float* Win0 = (const float*)d_in[1];
    const float* W0   = (const float*)d_in[2];
    const float* b0   = (const float*)d_in[3];
    const float* Win1 = (const float*)d_in[4];
    const float* W1   = (const float*)d_in[5];
    const float* b1   = (const float*)d_in[6];
    const float* Win2 = (const float*)d_in[7];
    const float* W2   = (const float*)d_in[8];
    const float* b2   = (const float*)d_in[9];
    const float* Wout = (const float*)d_in[10];
    const float* bout = (const float*)d_in[11];
    float* out = (float*)d_out;

    // recur smem: 64x516 + 16x516 + 128x66 = 198,912 B (1 CTA/SM)
    const int smem = (NCOL * SSTR + BCR * SSTR + 128 * RSTR) * (int)sizeof(float);
    static int attr_done = 0;
    if (!attr_done) {
        cudaFuncSetAttribute(recur_kernel,
                             cudaFuncAttributeMaxDynamicSharedMemorySize, smem);
        attr_done = 1;
    }

    const dim3 ggrid(4, (BB * TT) / 128);
    const dim3 hgrid(2, (BB * TT) / 128);

    init_kernel<<<3072, NT>>>();                             // launch 1
    drive_gemm<<<hgrid, NT>>>(x, Win0, b0, 64, 0, 0);        // launch 2
    drive_gemm<<<hgrid, NT>>>(x, Win0, b0, 64, 0, 256);      // launch 3
    recur_kernel<<<NGRP * NSLC, NTR, smem>>>(W0, 0);         // launch 4 (ncu aim)
    drive_gemm<<<ggrid, NT>>>(x, Win1, b1, 512, 1, 0);
    recur_kernel<<<NGRP * NSLC, NTR, smem>>>(W1, 1);
    drive_gemm<<<ggrid, NT>>>(x, Win2, b2, 512, 2, 0);
    recur_kernel<<<NGRP * NSLC, NTR, smem>>>(W2, 2);
    readout_kernel<<<BB, NT>>>(Wout, bout, out);
}